// round 16
// baseline (speedup 1.0000x reference)
#include <cuda_runtime.h>

#define B_    16
#define L_    8192
#define CH_   32
#define NBLK  24
#define TILE  256
#define PSTR  260     // row stride ≡ 4 (mod 32), 16B aligned -> conflict-free
#define NTHR  512
#define NTILE 512     // tiles per layer = (L_/TILE) * B_
#define NGRID ((NBLK+1)*NTILE)   // +1 pool "layer"

typedef unsigned long long u64;

// Scratch (device globals: allocation-free per harness rules).
// h buffers stored TRANSPOSED: [B][CH][L]. g_flags/g_pool start BSS-zero;
// fc_kernel re-zeroes them per call for graph-replay determinism.
__device__ float g_hi[B_*CH_*L_];
__device__ float g_ha[B_*CH_*L_];
__device__ float g_hb[B_*CH_*L_];
__device__ float g_pool[B_*128];
__device__ int   g_flags[NBLK*NTILE];

// ---- packed f32x2 helpers (FFMA2 is PTX-only; ptxas won't auto-fuse) ------
__device__ __forceinline__ u64 pack2(float a, float b) {
    u64 r; asm("mov.b64 %0, {%1,%2};" : "=l"(r) : "f"(a), "f"(b)); return r;
}
__device__ __forceinline__ void unpack2(u64 v, float& a, float& b) {
    asm("mov.b64 {%0,%1}, %2;" : "=f"(a), "=f"(b) : "l"(v));
}
__device__ __forceinline__ void fma2(u64& d, u64 a, u64 b) {
    asm("fma.rn.f32x2 %0, %1, %2, %0;" : "+l"(d) : "l"(a), "l"(b));
}

// gated = tanh(f)*sigmoid(g) = tanh(f) * (0.5*tanh(g/2) + 0.5): 2x MUFU.TANH
__device__ __forceinline__ float gate(float f, float g) {
    float t, s;
    asm("tanh.approx.f32 %0, %1;" : "=f"(t) : "f"(f));
    float gh = g * 0.5f;
    asm("tanh.approx.f32 %0, %1;" : "=f"(s) : "f"(gh));
    return t * fmaf(s, 0.5f, 0.5f);
}

// ---- acquire/release flag ops ---------------------------------------------
__device__ __forceinline__ int ld_acq(const int* p) {
    int v; asm volatile("ld.acquire.gpu.global.b32 %0, [%1];" : "=r"(v) : "l"(p) : "memory");
    return v;
}
__device__ __forceinline__ void st_rel(int* p, int v) {
    asm volatile("st.release.gpu.global.b32 [%0], %1;" :: "l"(p), "r"(v) : "memory");
}

// Channel-pair packed weights: FFMA2 weight operands come straight from LDS.
struct __align__(16) Smem {
    float4 wq[32][33];
    float4 w1q[32][8];
    float  bdf[32], bdg[32], b1s[32];
    float  hTc[32][PSTR];   // [c][pos]
    float  hTpg[32][PSTR];  // h[pos-dil] during conv, then reused for gated
};
#define SMEM_BYTES ((int)sizeof(Smem))

// ---------------------------------------------------------------------------
// 24 residual blocks + fused pool, one persistent flag-chained grid.
// bid = layer*NTILE + tile; layer NBLK = pool pass. TILE=256 halves CTA count
// vs R14 (amortizes weight staging / syncs / flags over 2x positions).
// ---------------------------------------------------------------------------
__global__ void __launch_bounds__(NTHR, 2) chain_kernel(
    const float* __restrict__ x,
    const float* __restrict__ W0,    const float* __restrict__ b0,
    const float* __restrict__ WdAll, const float* __restrict__ bdAll,
    const float* __restrict__ W1All, const float* __restrict__ b1All,
    const float* __restrict__ Wf,    const float* __restrict__ bf)
{
    extern __shared__ char smem_raw[];
    Smem& S = *reinterpret_cast<Smem*>(smem_raw);

    const int tid  = threadIdx.x;
    const int bid  = blockIdx.x;
    const int i    = bid >> 9;           // layer (NBLK = pool pass)
    const int tile = bid & (NTILE - 1);
    const int b    = tile >> 5;          // 32 tiles per batch
    const int tt   = tile & 31;
    const int l0   = tt * TILE;

    const int w    = tid >> 5;           // 16 warps
    const int lane = tid & 31;
    const int og   = (tid >> 2) & 7;     // channel-pair group
    const int pg   = tid & 3;            // position group
    const int pb4  = w*16 + 4*pg;        // this thread's 4 positions (0..252)

    // ======================= POOL PASS (i == NBLK) =========================
    if (i == NBLK) {
        if (tid < 256) {
            int og_ = tid & 7, c = tid >> 3;
            S.w1q[c][og_] = make_float4(Wf[(2*og_   )*32 + c], Wf[(2*og_+ 1)*32 + c],
                                        Wf[(2*og_+16)*32 + c], Wf[(2*og_+17)*32 + c]);
        }
        if (tid < 32) S.b1s[tid] = bf[tid];

        if (tid == 0) {
            int* f = &g_flags[(NBLK-1)*NTILE + tile];
            while (ld_acq(f) == 0) __nanosleep(64);
        }
        __syncthreads();

        // stage sv = relu(h_fin - h_init), [c][pos]; float4 streams
        {
            const float* hfb = g_hb + b*CH_*L_;
            const float* hib = g_hi + b*CH_*L_;
            #pragma unroll
            for (int cc = 0; cc < 2; cc++) {
                int c = w*2 + cc;
                #pragma unroll
                for (int q = 0; q < 2; q++) {
                    int p = lane*4 + q*128;
                    float4 vf = *(const float4*)&hfb[c*L_ + l0 + p];
                    float4 vi = *(const float4*)&hib[c*L_ + l0 + p];
                    float4 s = make_float4(fmaxf(vf.x - vi.x, 0.f),
                                           fmaxf(vf.y - vi.y, 0.f),
                                           fmaxf(vf.z - vi.z, 0.f),
                                           fmaxf(vf.w - vi.w, 0.f));
                    *(float4*)&S.hTc[c][p] = s;
                }
            }
        }
        __syncthreads();

        // y = relu(Wf @ sv + bf), channel-pair FFMA2 matvec
        u64 accA[4], accB[4];
        {
            u64 bA = *(const u64*)&S.b1s[2*og], bB = *(const u64*)&S.b1s[2*og+16];
            #pragma unroll
            for (int k = 0; k < 4; k++) { accA[k] = bA; accB[k] = bB; }
        }
        #pragma unroll 8
        for (int c = 0; c < 32; c++) {
            float4 gg = *(const float4*)&S.hTc[c][pb4];
            u64 d0 = pack2(gg.x, gg.x), d1 = pack2(gg.y, gg.y);
            u64 d2 = pack2(gg.z, gg.z), d3 = pack2(gg.w, gg.w);
            ulonglong2 wp = *(const ulonglong2*)&S.w1q[c][og];
            fma2(accA[0], wp.x, d0); fma2(accB[0], wp.y, d0);
            fma2(accA[1], wp.x, d1); fma2(accB[1], wp.y, d1);
            fma2(accA[2], wp.x, d2); fma2(accB[2], wp.y, d2);
            fma2(accA[3], wp.x, d3); fma2(accB[3], wp.y, d3);
        }
        float m0 = 0.f, m1 = 0.f, m2 = 0.f, m3 = 0.f;
        #pragma unroll
        for (int k = 0; k < 4; k++) {
            float a0, a1, b0v, b1v;
            unpack2(accA[k], a0, a1);
            unpack2(accB[k], b0v, b1v);
            m0 = fmaxf(m0, a0); m1 = fmaxf(m1, a1);
            m2 = fmaxf(m2, b0v); m3 = fmaxf(m3, b1v);
        }
        #pragma unroll
        for (int d = 1; d <= 2; d <<= 1) {
            m0 = fmaxf(m0, __shfl_xor_sync(0xffffffffu, m0, d));
            m1 = fmaxf(m1, __shfl_xor_sync(0xffffffffu, m1, d));
            m2 = fmaxf(m2, __shfl_xor_sync(0xffffffffu, m2, d));
            m3 = fmaxf(m3, __shfl_xor_sync(0xffffffffu, m3, d));
        }
        if (pg == 0) {
            int q = tt >> 3;   // 8 tiles (of 256) per L/4 chunk
            int* pool = (int*)g_pool + b*128;
            atomicMax(&pool[(2*og   )*4 + q], __float_as_int(m0));
            atomicMax(&pool[(2*og+ 1)*4 + q], __float_as_int(m1));
            atomicMax(&pool[(2*og+16)*4 + q], __float_as_int(m2));
            atomicMax(&pool[(2*og+17)*4 + q], __float_as_int(m3));
        }
        return;
    }

    // ======================= RESIDUAL BLOCK PASS ===========================
    const int dil  = 1 << (i & 7);
    const float* Wd = WdAll + i*64*32*2;
    const float* bd = bdAll + i*64;
    const float* W1 = W1All + i*1024;
    const float* b1 = b1All + i*32;
    const float* h_in = (i & 1) ? g_ha : g_hb;   // only used for i > 0
    float*       h_out = (i & 1) ? g_hb : g_ha;

    // ---- stage weights first (independent of producer layer)
    const float2* Wd2 = (const float2*)Wd;
    #pragma unroll
    for (int idx = tid; idx < 1024; idx += NTHR) {
        int j = idx >> 5, c = idx & 31;
        int o0 = 2*(j & 15) + ((j >= 16) ? 32 : 0);
        float2 wa = Wd2[o0*32 + c];
        float2 wb = Wd2[(o0+1)*32 + c];
        S.wq[c][j] = make_float4(wa.x, wb.x, wa.y, wb.y);
    }
    if (tid < 256) {
        int og_ = tid & 7, c = tid >> 3;
        S.w1q[c][og_] = make_float4(W1[(2*og_   )*32 + c], W1[(2*og_+ 1)*32 + c],
                                    W1[(2*og_+16)*32 + c], W1[(2*og_+17)*32 + c]);
    }
    if (tid < 32) { S.bdf[tid] = bd[tid]; S.bdg[tid] = bd[32 + tid]; S.b1s[tid] = b1[tid]; }

    if (i == 0) {
        // ---- layer 0: compute h_init from x inline (bitwise-identical order)
        const float* xb = x + b*L_;
        const int c0 = tid & 31;
        const float w0a = W0[2*c0], w0b = W0[2*c0 + 1], bb0 = b0[c0];
        #pragma unroll
        for (int n = 0; n < 4; n++) {
            int lq = ((tid >> 5) + 16*n) * 4;      // 0..252
            int l = l0 + lq;
            float xm2 = (l >= 2) ? xb[l-2] : 0.f;
            float xm1 = (l >= 1) ? xb[l-1] : 0.f;
            float x0 = xb[l], x1 = xb[l+1], x2 = xb[l+2], x3 = xb[l+3];
            float hm1 = (l >= 1) ? fmaf(w0a, xm2, fmaf(w0b, xm1, bb0)) : 0.f;
            float h0  = fmaf(w0a, xm1, fmaf(w0b, x0, bb0));
            float h1  = fmaf(w0a, x0,  fmaf(w0b, x1, bb0));
            float h2  = fmaf(w0a, x1,  fmaf(w0b, x2, bb0));
            float h3  = fmaf(w0a, x2,  fmaf(w0b, x3, bb0));
            *(float4*)&S.hTc[c0][lq]  = make_float4(h0, h1, h2, h3);
            *(float4*)&S.hTpg[c0][lq] = make_float4(hm1, h0, h1, h2);
        }
        __syncthreads();
        // persist h_init transposed (coalesced float4 rows)
        #pragma unroll
        for (int cc = 0; cc < 2; cc++) {
            int c = w*2 + cc;
            #pragma unroll
            for (int q = 0; q < 2; q++) {
                int p = lane*4 + q*128;
                float4 v = *(const float4*)&S.hTc[c][p];
                *(float4*)&g_hi[(b*CH_ + c)*L_ + l0 + p] = v;
            }
        }
    } else {
        // ---- wait for producer tiles (acquire-load spin)
        if (tid == 0) {
            int* f = &g_flags[(i-1)*NTILE + tile];
            while (ld_acq(f) == 0) __nanosleep(64);
            if (tt > 0)
                while (ld_acq(f - 1) == 0) __nanosleep(64);
        }
        __syncthreads();

        // ---- stage h tiles: transposed global -> pure float4 streams
        const float* hinb = h_in + b*CH_*L_;
        const bool fastp = (dil >= 4) && (l0 >= dil);
        #pragma unroll
        for (int cc = 0; cc < 2; cc++) {
            const int c = w*2 + cc;
            const float* rowc = hinb + c*L_;
            #pragma unroll
            for (int q = 0; q < 2; q++) {
                int p = lane*4 + q*128;
                float4 vc = *(const float4*)&rowc[l0 + p];
                *(float4*)&S.hTc[c][p] = vc;
                if (fastp) {
                    float4 vp = *(const float4*)&rowc[l0 - dil + p];
                    *(float4*)&S.hTpg[c][p] = vp;
                } else {
                    int lb = l0 + p - dil;
                    float4 vp;
                    vp.x = (lb   >= 0) ? rowc[lb  ] : 0.f;
                    vp.y = (lb+1 >= 0) ? rowc[lb+1] : 0.f;
                    vp.z = (lb+2 >= 0) ? rowc[lb+2] : 0.f;
                    vp.w = (lb+3 >= 0) ? rowc[lb+3] : 0.f;
                    *(float4*)&S.hTpg[c][p] = vp;
                }
            }
        }
        __syncthreads();
    }

    // ---- dilated conv: acc = packed channel-pair, per position
    u64 accfA[4], accfB[4], accgA[4], accgB[4];
    {
        u64 bfA = *(const u64*)&S.bdf[2*og], bfB = *(const u64*)&S.bdf[2*og+16];
        u64 bgA = *(const u64*)&S.bdg[2*og], bgB = *(const u64*)&S.bdg[2*og+16];
        #pragma unroll
        for (int k = 0; k < 4; k++) {
            accfA[k] = bfA; accfB[k] = bfB; accgA[k] = bgA; accgB[k] = bgB;
        }
    }
    #pragma unroll 8
    for (int c = 0; c < 32; c++) {
        float4 hp4 = *(const float4*)&S.hTpg[c][pb4];
        float4 hc4 = *(const float4*)&S.hTc[c][pb4];
        u64 dp[4], dc[4];
        dp[0] = pack2(hp4.x, hp4.x); dp[1] = pack2(hp4.y, hp4.y);
        dp[2] = pack2(hp4.z, hp4.z); dp[3] = pack2(hp4.w, hp4.w);
        dc[0] = pack2(hc4.x, hc4.x); dc[1] = pack2(hc4.y, hc4.y);
        dc[2] = pack2(hc4.z, hc4.z); dc[3] = pack2(hc4.w, hc4.w);
        ulonglong2 wfA = *(const ulonglong2*)&S.wq[c][og];
        #pragma unroll
        for (int k = 0; k < 4; k++) { fma2(accfA[k], wfA.x, dp[k]); fma2(accfA[k], wfA.y, dc[k]); }
        ulonglong2 wfB = *(const ulonglong2*)&S.wq[c][og + 8];
        #pragma unroll
        for (int k = 0; k < 4; k++) { fma2(accfB[k], wfB.x, dp[k]); fma2(accfB[k], wfB.y, dc[k]); }
        ulonglong2 wgA = *(const ulonglong2*)&S.wq[c][16 + og];
        #pragma unroll
        for (int k = 0; k < 4; k++) { fma2(accgA[k], wgA.x, dp[k]); fma2(accgA[k], wgA.y, dc[k]); }
        ulonglong2 wgB = *(const ulonglong2*)&S.wq[c][24 + og];
        #pragma unroll
        for (int k = 0; k < 4; k++) { fma2(accgB[k], wgB.x, dp[k]); fma2(accgB[k], wgB.y, dc[k]); }
    }

    // ---- gating; write gated rows into hTpg (warp-local column stripe reuse)
    __syncwarp();
    {
        float rA0[4], rA1[4], rB0[4], rB1[4];
        #pragma unroll
        for (int k = 0; k < 4; k++) {
            float fa0, fa1, ga0, ga1, fb0, fb1, gb0, gb1;
            unpack2(accfA[k], fa0, fa1); unpack2(accgA[k], ga0, ga1);
            unpack2(accfB[k], fb0, fb1); unpack2(accgB[k], gb0, gb1);
            rA0[k] = gate(fa0, ga0); rA1[k] = gate(fa1, ga1);
            rB0[k] = gate(fb0, gb0); rB1[k] = gate(fb1, gb1);
        }
        *(float4*)&S.hTpg[2*og   ][pb4] = make_float4(rA0[0], rA0[1], rA0[2], rA0[3]);
        *(float4*)&S.hTpg[2*og+ 1][pb4] = make_float4(rA1[0], rA1[1], rA1[2], rA1[3]);
        *(float4*)&S.hTpg[2*og+16][pb4] = make_float4(rB0[0], rB0[1], rB0[2], rB0[3]);
        *(float4*)&S.hTpg[2*og+17][pb4] = make_float4(rB1[0], rB1[1], rB1[2], rB1[3]);
    }
    __syncwarp();

    // ---- skip = W1 @ gated + b1
    u64 accsA[4], accsB[4];
    {
        u64 bsA = *(const u64*)&S.b1s[2*og], bsB = *(const u64*)&S.b1s[2*og+16];
        #pragma unroll
        for (int k = 0; k < 4; k++) { accsA[k] = bsA; accsB[k] = bsB; }
    }
    #pragma unroll 8
    for (int c = 0; c < 32; c++) {
        float4 gg = *(const float4*)&S.hTpg[c][pb4];
        u64 d0 = pack2(gg.x, gg.x), d1 = pack2(gg.y, gg.y);
        u64 d2 = pack2(gg.z, gg.z), d3 = pack2(gg.w, gg.w);
        ulonglong2 wp = *(const ulonglong2*)&S.w1q[c][og];
        fma2(accsA[0], wp.x, d0); fma2(accsB[0], wp.y, d0);
        fma2(accsA[1], wp.x, d1); fma2(accsB[1], wp.y, d1);
        fma2(accsA[2], wp.x, d2); fma2(accsB[2], wp.y, d2);
        fma2(accsA[3], wp.x, d3); fma2(accsB[3], wp.y, d3);
    }

    // ---- residual: h_out = h_in + skip; transposed rows -> 4x STG.128
    {
        float4 h0 = *(const float4*)&S.hTc[2*og   ][pb4];
        float4 h1 = *(const float4*)&S.hTc[2*og+ 1][pb4];
        float4 h2 = *(const float4*)&S.hTc[2*og+16][pb4];
        float4 h3 = *(const float4*)&S.hTc[2*og+17][pb4];
        float sa0[4], sa1[4], sb0[4], sb1[4];
        #pragma unroll
        for (int k = 0; k < 4; k++) {
            unpack2(accsA[k], sa0[k], sa1[k]);
            unpack2(accsB[k], sb0[k], sb1[k]);
        }
        float* houtb = h_out + b*CH_*L_;
        *(float4*)&houtb[(2*og   )*L_ + l0 + pb4] =
            make_float4(h0.x + sa0[0], h0.y + sa0[1], h0.z + sa0[2], h0.w + sa0[3]);
        *(float4*)&houtb[(2*og+ 1)*L_ + l0 + pb4] =
            make_float4(h1.x + sa1[0], h1.y + sa1[1], h1.z + sa1[2], h1.w + sa1[3]);
        *(float4*)&houtb[(2*og+16)*L_ + l0 + pb4] =
            make_float4(h2.x + sb0[0], h2.y + sb0[1], h2.z + sb0[2], h2.w + sb0[3]);
        *(float4*)&houtb[(2*og+17)*L_ + l0 + pb4] =
            make_float4(h3.x + sb1[0], h3.y + sb1[1], h3.z + sb1[2], h3.w + sb1[3]);
    }

    // ---- publish this tile's completion (release store after CTA barrier)
    __syncthreads();
    if (tid == 0)
        st_rel(&g_flags[i*NTILE + tile], 1);
}

// ---------------------------------------------------------------------------
// FC head: 128 -> 64 (relu) -> 10. PDL; resets g_flags/g_pool for next replay.
// ---------------------------------------------------------------------------
__global__ void fc_kernel(const float* __restrict__ fW1, const float* __restrict__ fb1,
                          const float* __restrict__ fW2, const float* __restrict__ fb2,
                          float* __restrict__ out)
{
    __shared__ float sw[64*129];
    __shared__ float ps[128], h1[64];
    const int b = blockIdx.x, tid = threadIdx.x;

    #pragma unroll 8
    for (int i = tid; i < 8192; i += 64) {
        int r = i >> 7, c = i & 127;
        sw[r*129 + c] = fW1[i];
    }
    float bias = fb1[tid];
    cudaGridDependencySynchronize();       // all chain CTAs (incl. pool) done

    ps[tid]      = g_pool[b*128 + tid];
    ps[tid + 64] = g_pool[b*128 + 64 + tid];
    __syncthreads();

    g_pool[b*128 + tid]      = 0.f;
    g_pool[b*128 + 64 + tid] = 0.f;
    for (int j = b*64 + tid; j < NBLK*NTILE; j += B_*64)
        g_flags[j] = 0;

    float acc = bias;
    #pragma unroll 16
    for (int k = 0; k < 128; k++) acc = fmaf(sw[tid*129 + k], ps[k], acc);
    h1[tid] = fmaxf(acc, 0.f);
    __syncthreads();
    if (tid < 10) {
        float a2 = fb2[tid];
        #pragma unroll 8
        for (int k = 0; k < 64; k++) a2 = fmaf(fW2[tid*64 + k], h1[k], a2);
        out[b*10 + tid] = a2;
    }
}

// ---------------------------------------------------------------------------
extern "C" void kernel_launch(void* const* d_in, const int* in_sizes, int n_in,
                              void* d_out, int out_size)
{
    const float* x   = (const float*)d_in[0];
    const float* W0  = (const float*)d_in[1];
    const float* b0  = (const float*)d_in[2];
    const float* Wd  = (const float*)d_in[3];   // (24, 64, 32, 2)
    const float* bd  = (const float*)d_in[4];   // (24, 64)
    const float* W1  = (const float*)d_in[5];   // (24, 32, 32)
    const float* b1  = (const float*)d_in[6];   // (24, 32)
    const float* Wf  = (const float*)d_in[7];
    const float* bf  = (const float*)d_in[8];
    const float* fW1 = (const float*)d_in[9];
    const float* fb1 = (const float*)d_in[10];
    const float* fW2 = (const float*)d_in[11];
    const float* fb2 = (const float*)d_in[12];
    float* out = (float*)d_out;

    static bool attr_done = false;
    if (!attr_done) {
        cudaFuncSetAttribute(chain_kernel,
            cudaFuncAttributeMaxDynamicSharedMemorySize, SMEM_BYTES);
        attr_done = true;
    }

    // 24 layers (layer 0 computes h_init from x) + fused pool, one grid
    chain_kernel<<<NGRID, NTHR, SMEM_BYTES>>>(x, W0, b0, Wd, bd, W1, b1, Wf, bf);

    // FC head with PDL: weight staging overlaps the chain tail
    cudaLaunchAttribute pdl[1];
    pdl[0].id = cudaLaunchAttributeProgrammaticStreamSerialization;
    pdl[0].val.programmaticStreamSerializationAllowed = 1;
    cudaLaunchConfig_t cfgF = {};
    cfgF.gridDim  = dim3(B_);
    cfgF.blockDim = dim3(64);
    cfgF.dynamicSmemBytes = 0;
    cfgF.stream = 0;
    cfgF.attrs = pdl;
    cfgF.numAttrs = 1;
    cudaLaunchKernelEx(&cfgF, fc_kernel, fW1, fb1, fW2, fb2, out);
}

// round 17
// speedup vs baseline: 1.0084x; 1.0084x over previous
#include <cuda_runtime.h>

#define B_    16
#define L_    8192
#define CH_   32
#define NBLK  24
#define TILE  128
#define PSTR  132     // row stride ≡ 4 (mod 32), 16B aligned
#define NTHR  256
#define NTILE 1024    // tiles per layer = (L_/TILE) * B_
#define NGRID ((NBLK+1)*NTILE)   // +1 pool "layer"

typedef unsigned long long u64;

// Scratch (device globals: allocation-free per harness rules).
// h buffers stored TRANSPOSED: [B][CH][L]. g_flags/g_pool start BSS-zero;
// fc_kernel re-zeroes them per call for graph-replay determinism.
__device__ float g_hi[B_*CH_*L_];
__device__ float g_ha[B_*CH_*L_];
__device__ float g_hb[B_*CH_*L_];
__device__ float g_pool[B_*128];
__device__ int   g_flags[NBLK*NTILE];

// ---- packed f32x2 helpers (FFMA2 is PTX-only; ptxas won't auto-fuse) ------
__device__ __forceinline__ u64 pack2(float a, float b) {
    u64 r; asm("mov.b64 %0, {%1,%2};" : "=l"(r) : "f"(a), "f"(b)); return r;
}
__device__ __forceinline__ void unpack2(u64 v, float& a, float& b) {
    asm("mov.b64 {%0,%1}, %2;" : "=f"(a), "=f"(b) : "l"(v));
}
__device__ __forceinline__ void fma2(u64& d, u64 a, u64 b) {
    asm("fma.rn.f32x2 %0, %1, %2, %0;" : "+l"(d) : "l"(a), "l"(b));
}

// gated = tanh(f)*sigmoid(g) = tanh(f) * (0.5*tanh(g/2) + 0.5): 2x MUFU.TANH
__device__ __forceinline__ float gate(float f, float g) {
    float t, s;
    asm("tanh.approx.f32 %0, %1;" : "=f"(t) : "f"(f));
    float gh = g * 0.5f;
    asm("tanh.approx.f32 %0, %1;" : "=f"(s) : "f"(gh));
    return t * fmaf(s, 0.5f, 0.5f);
}

// ---- acquire/release flag ops ---------------------------------------------
__device__ __forceinline__ int ld_acq(const int* p) {
    int v; asm volatile("ld.acquire.gpu.global.b32 %0, [%1];" : "=r"(v) : "l"(p) : "memory");
    return v;
}
__device__ __forceinline__ void st_rel(int* p, int v) {
    asm volatile("st.release.gpu.global.b32 [%0], %1;" :: "l"(p), "r"(v) : "memory");
}

// Per-warp producer wait: lane 0 acquire-spins, then warp barrier. Gives the
// same leader-acquire ordering the old (tid==0 spin + __syncthreads) gave,
// but each warp starts its own staging LDGs as soon as ITS wait passes.
__device__ __forceinline__ void warp_wait_flags(const int* f, bool need_prev, int lane) {
    if (lane == 0) {
        while (ld_acq(f) == 0) __nanosleep(64);
        if (need_prev)
            while (ld_acq(f - 1) == 0) __nanosleep(64);
    }
    __syncwarp();
}

// Channel-pair packed weights: FFMA2 weight operands come straight from LDS.
struct __align__(16) Smem {
    float4 wq[32][33];
    float4 w1q[32][8];
    float  bdf[32], bdg[32], b1s[32];
    float  hTc[32][PSTR];   // [c][pos]
    float  hTpg[32][PSTR];  // h[pos-dil] during conv, then reused for gated
};
#define SMEM_BYTES ((int)sizeof(Smem))

// ---------------------------------------------------------------------------
// 24 residual blocks + fused pool, one persistent flag-chained grid.
// ---------------------------------------------------------------------------
__global__ void __launch_bounds__(NTHR, 4) chain_kernel(
    const float* __restrict__ x,
    const float* __restrict__ W0,    const float* __restrict__ b0,
    const float* __restrict__ WdAll, const float* __restrict__ bdAll,
    const float* __restrict__ W1All, const float* __restrict__ b1All,
    const float* __restrict__ Wf,    const float* __restrict__ bf)
{
    extern __shared__ char smem_raw[];
    Smem& S = *reinterpret_cast<Smem*>(smem_raw);

    const int tid  = threadIdx.x;
    const int bid  = blockIdx.x;
    const int i    = bid >> 10;          // layer (NBLK = pool pass)
    const int tile = bid & (NTILE - 1);
    const int b    = tile >> 6;
    const int tt   = tile & 63;
    const int l0   = tt * TILE;

    const int w    = tid >> 5;
    const int lane = tid & 31;
    const int og   = (tid >> 2) & 7;    // channel-pair group
    const int pg   = tid & 3;           // position group
    const int pb4  = w*16 + 4*pg;       // this thread's 4 positions

    // ======================= POOL PASS (i == NBLK) =========================
    if (i == NBLK) {
        {
            int og_ = tid & 7, c = tid >> 3;
            S.w1q[c][og_] = make_float4(Wf[(2*og_   )*32 + c], Wf[(2*og_+ 1)*32 + c],
                                        Wf[(2*og_+16)*32 + c], Wf[(2*og_+17)*32 + c]);
        }
        if (tid < 32) S.b1s[tid] = bf[tid];

        // per-warp wait, then stage own channel rows immediately
        warp_wait_flags(&g_flags[(NBLK-1)*NTILE + tile], false, lane);
        {
            const float* hfb = g_hb + b*CH_*L_;
            const float* hib = g_hi + b*CH_*L_;
            #pragma unroll
            for (int cc = 0; cc < 4; cc++) {
                int c = w*4 + cc;
                float4 vf = *(const float4*)&hfb[c*L_ + l0 + lane*4];
                float4 vi = *(const float4*)&hib[c*L_ + l0 + lane*4];
                float4 s = make_float4(fmaxf(vf.x - vi.x, 0.f),
                                       fmaxf(vf.y - vi.y, 0.f),
                                       fmaxf(vf.z - vi.z, 0.f),
                                       fmaxf(vf.w - vi.w, 0.f));
                *(float4*)&S.hTc[c][lane*4] = s;
            }
        }
        __syncthreads();

        // y = relu(Wf @ sv + bf), channel-pair FFMA2 matvec
        u64 accA[4], accB[4];
        {
            u64 bA = *(const u64*)&S.b1s[2*og], bB = *(const u64*)&S.b1s[2*og+16];
            #pragma unroll
            for (int k = 0; k < 4; k++) { accA[k] = bA; accB[k] = bB; }
        }
        #pragma unroll 8
        for (int c = 0; c < 32; c++) {
            float4 gg = *(const float4*)&S.hTc[c][pb4];
            u64 d0 = pack2(gg.x, gg.x), d1 = pack2(gg.y, gg.y);
            u64 d2 = pack2(gg.z, gg.z), d3 = pack2(gg.w, gg.w);
            ulonglong2 wp = *(const ulonglong2*)&S.w1q[c][og];
            fma2(accA[0], wp.x, d0); fma2(accB[0], wp.y, d0);
            fma2(accA[1], wp.x, d1); fma2(accB[1], wp.y, d1);
            fma2(accA[2], wp.x, d2); fma2(accB[2], wp.y, d2);
            fma2(accA[3], wp.x, d3); fma2(accB[3], wp.y, d3);
        }
        float m0 = 0.f, m1 = 0.f, m2 = 0.f, m3 = 0.f;
        #pragma unroll
        for (int k = 0; k < 4; k++) {
            float a0, a1, b0v, b1v;
            unpack2(accA[k], a0, a1);
            unpack2(accB[k], b0v, b1v);
            m0 = fmaxf(m0, a0); m1 = fmaxf(m1, a1);
            m2 = fmaxf(m2, b0v); m3 = fmaxf(m3, b1v);
        }
        #pragma unroll
        for (int d = 1; d <= 2; d <<= 1) {
            m0 = fmaxf(m0, __shfl_xor_sync(0xffffffffu, m0, d));
            m1 = fmaxf(m1, __shfl_xor_sync(0xffffffffu, m1, d));
            m2 = fmaxf(m2, __shfl_xor_sync(0xffffffffu, m2, d));
            m3 = fmaxf(m3, __shfl_xor_sync(0xffffffffu, m3, d));
        }
        if (pg == 0) {
            int q = tt >> 4;
            int* pool = (int*)g_pool + b*128;
            atomicMax(&pool[(2*og   )*4 + q], __float_as_int(m0));
            atomicMax(&pool[(2*og+ 1)*4 + q], __float_as_int(m1));
            atomicMax(&pool[(2*og+16)*4 + q], __float_as_int(m2));
            atomicMax(&pool[(2*og+17)*4 + q], __float_as_int(m3));
        }
        return;
    }

    // ======================= RESIDUAL BLOCK PASS ===========================
    const int dil  = 1 << (i & 7);
    const float* Wd = WdAll + i*64*32*2;
    const float* bd = bdAll + i*64;
    const float* W1 = W1All + i*1024;
    const float* b1 = b1All + i*32;
    const float* h_in = (i & 1) ? g_ha : g_hb;   // only used for i > 0
    float*       h_out = (i & 1) ? g_hb : g_ha;

    // ---- stage weights first (independent of producer layer)
    const float2* Wd2 = (const float2*)Wd;
    #pragma unroll
    for (int idx = tid; idx < 1024; idx += NTHR) {
        int j = idx >> 5, c = idx & 31;
        int o0 = 2*(j & 15) + ((j >= 16) ? 32 : 0);
        float2 wa = Wd2[o0*32 + c];
        float2 wb = Wd2[(o0+1)*32 + c];
        S.wq[c][j] = make_float4(wa.x, wb.x, wa.y, wb.y);
    }
    {
        int og_ = tid & 7, c = tid >> 3;
        S.w1q[c][og_] = make_float4(W1[(2*og_   )*32 + c], W1[(2*og_+ 1)*32 + c],
                                    W1[(2*og_+16)*32 + c], W1[(2*og_+17)*32 + c]);
    }
    if (tid < 32) { S.bdf[tid] = bd[tid]; S.bdg[tid] = bd[32 + tid]; S.b1s[tid] = b1[tid]; }

    if (i == 0) {
        // ---- layer 0: compute h_init from x inline (bitwise-identical order)
        const float* xb = x + b*L_;
        const int c0 = tid & 31;
        const float w0a = W0[2*c0], w0b = W0[2*c0 + 1], bb0 = b0[c0];
        #pragma unroll
        for (int n = 0; n < 4; n++) {
            int lq = ((tid >> 5) + 8*n) * 4;
            int l = l0 + lq;
            float xm2 = (l >= 2) ? xb[l-2] : 0.f;
            float xm1 = (l >= 1) ? xb[l-1] : 0.f;
            float x0 = xb[l], x1 = xb[l+1], x2 = xb[l+2], x3 = xb[l+3];
            float hm1 = (l >= 1) ? fmaf(w0a, xm2, fmaf(w0b, xm1, bb0)) : 0.f;
            float h0  = fmaf(w0a, xm1, fmaf(w0b, x0, bb0));
            float h1  = fmaf(w0a, x0,  fmaf(w0b, x1, bb0));
            float h2  = fmaf(w0a, x1,  fmaf(w0b, x2, bb0));
            float h3  = fmaf(w0a, x2,  fmaf(w0b, x3, bb0));
            *(float4*)&S.hTc[c0][lq]  = make_float4(h0, h1, h2, h3);
            *(float4*)&S.hTpg[c0][lq] = make_float4(hm1, h0, h1, h2);
        }
        __syncthreads();
        #pragma unroll
        for (int cc = 0; cc < 4; cc++) {
            int c = w*4 + cc;
            float4 v = *(const float4*)&S.hTc[c][lane*4];
            *(float4*)&g_hi[(b*CH_ + c)*L_ + l0 + lane*4] = v;
        }
    } else {
        // ---- per-warp wait, then stage own channel rows immediately
        warp_wait_flags(&g_flags[(i-1)*NTILE + tile], tt > 0, lane);

        const float* hinb = h_in + b*CH_*L_;
        const bool fastp = (dil >= 4) && (l0 >= dil);
        #pragma unroll
        for (int cc = 0; cc < 4; cc++) {
            const int c = w*4 + cc;
            const float* rowc = hinb + c*L_;
            float4 vc = *(const float4*)&rowc[l0 + lane*4];
            *(float4*)&S.hTc[c][lane*4] = vc;
            if (fastp) {
                float4 vp = *(const float4*)&rowc[l0 - dil + lane*4];
                *(float4*)&S.hTpg[c][lane*4] = vp;
            } else {
                int lb = l0 + lane*4 - dil;
                float4 vp;
                vp.x = (lb   >= 0) ? rowc[lb  ] : 0.f;
                vp.y = (lb+1 >= 0) ? rowc[lb+1] : 0.f;
                vp.z = (lb+2 >= 0) ? rowc[lb+2] : 0.f;
                vp.w = (lb+3 >= 0) ? rowc[lb+3] : 0.f;
                *(float4*)&S.hTpg[c][lane*4] = vp;
            }
        }
        __syncthreads();
    }

    // ---- dilated conv: acc = packed channel-pair, per position
    u64 accfA[4], accfB[4], accgA[4], accgB[4];
    {
        u64 bfA = *(const u64*)&S.bdf[2*og], bfB = *(const u64*)&S.bdf[2*og+16];
        u64 bgA = *(const u64*)&S.bdg[2*og], bgB = *(const u64*)&S.bdg[2*og+16];
        #pragma unroll
        for (int k = 0; k < 4; k++) {
            accfA[k] = bfA; accfB[k] = bfB; accgA[k] = bgA; accgB[k] = bgB;
        }
    }
    #pragma unroll 8
    for (int c = 0; c < 32; c++) {
        float4 hp4 = *(const float4*)&S.hTpg[c][pb4];
        float4 hc4 = *(const float4*)&S.hTc[c][pb4];
        u64 dp[4], dc[4];
        dp[0] = pack2(hp4.x, hp4.x); dp[1] = pack2(hp4.y, hp4.y);
        dp[2] = pack2(hp4.z, hp4.z); dp[3] = pack2(hp4.w, hp4.w);
        dc[0] = pack2(hc4.x, hc4.x); dc[1] = pack2(hc4.y, hc4.y);
        dc[2] = pack2(hc4.z, hc4.z); dc[3] = pack2(hc4.w, hc4.w);
        ulonglong2 wfA = *(const ulonglong2*)&S.wq[c][og];
        #pragma unroll
        for (int k = 0; k < 4; k++) { fma2(accfA[k], wfA.x, dp[k]); fma2(accfA[k], wfA.y, dc[k]); }
        ulonglong2 wfB = *(const ulonglong2*)&S.wq[c][og + 8];
        #pragma unroll
        for (int k = 0; k < 4; k++) { fma2(accfB[k], wfB.x, dp[k]); fma2(accfB[k], wfB.y, dc[k]); }
        ulonglong2 wgA = *(const ulonglong2*)&S.wq[c][16 + og];
        #pragma unroll
        for (int k = 0; k < 4; k++) { fma2(accgA[k], wgA.x, dp[k]); fma2(accgA[k], wgA.y, dc[k]); }
        ulonglong2 wgB = *(const ulonglong2*)&S.wq[c][24 + og];
        #pragma unroll
        for (int k = 0; k < 4; k++) { fma2(accgB[k], wgB.x, dp[k]); fma2(accgB[k], wgB.y, dc[k]); }
    }

    // ---- gating; write gated rows into hTpg (warp-local column stripe reuse)
    __syncwarp();
    {
        float rA0[4], rA1[4], rB0[4], rB1[4];
        #pragma unroll
        for (int k = 0; k < 4; k++) {
            float fa0, fa1, ga0, ga1, fb0, fb1, gb0, gb1;
            unpack2(accfA[k], fa0, fa1); unpack2(accgA[k], ga0, ga1);
            unpack2(accfB[k], fb0, fb1); unpack2(accgB[k], gb0, gb1);
            rA0[k] = gate(fa0, ga0); rA1[k] = gate(fa1, ga1);
            rB0[k] = gate(fb0, gb0); rB1[k] = gate(fb1, gb1);
        }
        *(float4*)&S.hTpg[2*og   ][pb4] = make_float4(rA0[0], rA0[1], rA0[2], rA0[3]);
        *(float4*)&S.hTpg[2*og+ 1][pb4] = make_float4(rA1[0], rA1[1], rA1[2], rA1[3]);
        *(float4*)&S.hTpg[2*og+16][pb4] = make_float4(rB0[0], rB0[1], rB0[2], rB0[3]);
        *(float4*)&S.hTpg[2*og+17][pb4] = make_float4(rB1[0], rB1[1], rB1[2], rB1[3]);
    }
    __syncwarp();

    // ---- skip = W1 @ gated + b1
    u64 accsA[4], accsB[4];
    {
        u64 bsA = *(const u64*)&S.b1s[2*og], bsB = *(const u64*)&S.b1s[2*og+16];
        #pragma unroll
        for (int k = 0; k < 4; k++) { accsA[k] = bsA; accsB[k] = bsB; }
    }
    #pragma unroll 8
    for (int c = 0; c < 32; c++) {
        float4 gg = *(const float4*)&S.hTpg[c][pb4];
        u64 d0 = pack2(gg.x, gg.x), d1 = pack2(gg.y, gg.y);
        u64 d2 = pack2(gg.z, gg.z), d3 = pack2(gg.w, gg.w);
        ulonglong2 wp = *(const ulonglong2*)&S.w1q[c][og];
        fma2(accsA[0], wp.x, d0); fma2(accsB[0], wp.y, d0);
        fma2(accsA[1], wp.x, d1); fma2(accsB[1], wp.y, d1);
        fma2(accsA[2], wp.x, d2); fma2(accsB[2], wp.y, d2);
        fma2(accsA[3], wp.x, d3); fma2(accsB[3], wp.y, d3);
    }

    // ---- residual: h_out = h_in + skip; transposed rows -> 4x STG.128
    {
        float4 h0 = *(const float4*)&S.hTc[2*og   ][pb4];
        float4 h1 = *(const float4*)&S.hTc[2*og+ 1][pb4];
        float4 h2 = *(const float4*)&S.hTc[2*og+16][pb4];
        float4 h3 = *(const float4*)&S.hTc[2*og+17][pb4];
        float sa0[4], sa1[4], sb0[4], sb1[4];
        #pragma unroll
        for (int k = 0; k < 4; k++) {
            unpack2(accsA[k], sa0[k], sa1[k]);
            unpack2(accsB[k], sb0[k], sb1[k]);
        }
        float* houtb = h_out + b*CH_*L_;
        *(float4*)&houtb[(2*og   )*L_ + l0 + pb4] =
            make_float4(h0.x + sa0[0], h0.y + sa0[1], h0.z + sa0[2], h0.w + sa0[3]);
        *(float4*)&houtb[(2*og+ 1)*L_ + l0 + pb4] =
            make_float4(h1.x + sa1[0], h1.y + sa1[1], h1.z + sa1[2], h1.w + sa1[3]);
        *(float4*)&houtb[(2*og+16)*L_ + l0 + pb4] =
            make_float4(h2.x + sb0[0], h2.y + sb0[1], h2.z + sb0[2], h2.w + sb0[3]);
        *(float4*)&houtb[(2*og+17)*L_ + l0 + pb4] =
            make_float4(h3.x + sb1[0], h3.y + sb1[1], h3.z + sb1[2], h3.w + sb1[3]);
    }

    // ---- publish this tile's completion (release store after CTA barrier)
    __syncthreads();
    if (tid == 0)
        st_rel(&g_flags[i*NTILE + tile], 1);
}

// ---------------------------------------------------------------------------
// FC head: 128 -> 64 (relu) -> 10. PDL; resets g_flags/g_pool for next replay.
// ---------------------------------------------------------------------------
__global__ void fc_kernel(const float* __restrict__ fW1, const float* __restrict__ fb1,
                          const float* __restrict__ fW2, const float* __restrict__ fb2,
                          float* __restrict__ out)
{
    __shared__ float sw[64*129];
    __shared__ float ps[128], h1[64];
    const int b = blockIdx.x, tid = threadIdx.x;

    #pragma unroll 8
    for (int i = tid; i < 8192; i += 64) {
        int r = i >> 7, c = i & 127;
        sw[r*129 + c] = fW1[i];
    }
    float bias = fb1[tid];
    cudaGridDependencySynchronize();       // all chain CTAs (incl. pool) done

    ps[tid]      = g_pool[b*128 + tid];
    ps[tid + 64] = g_pool[b*128 + 64 + tid];
    __syncthreads();

    g_pool[b*128 + tid]      = 0.f;
    g_pool[b*128 + 64 + tid] = 0.f;
    for (int j = b*64 + tid; j < NBLK*NTILE; j += B_*64)
        g_flags[j] = 0;

    float acc = bias;
    #pragma unroll 16
    for (int k = 0; k < 128; k++) acc = fmaf(sw[tid*129 + k], ps[k], acc);
    h1[tid] = fmaxf(acc, 0.f);
    __syncthreads();
    if (tid < 10) {
        float a2 = fb2[tid];
        #pragma unroll 8
        for (int k = 0; k < 64; k++) a2 = fmaf(fW2[tid*64 + k], h1[k], a2);
        out[b*10 + tid] = a2;
    }
}

// ---------------------------------------------------------------------------
extern "C" void kernel_launch(void* const* d_in, const int* in_sizes, int n_in,
                              void* d_out, int out_size)
{
    const float* x   = (const float*)d_in[0];
    const float* W0  = (const float*)d_in[1];
    const float* b0  = (const float*)d_in[2];
    const float* Wd  = (const float*)d_in[3];   // (24, 64, 32, 2)
    const float* bd  = (const float*)d_in[4];   // (24, 64)
    const float* W1  = (const float*)d_in[5];   // (24, 32, 32)
    const float* b1  = (const float*)d_in[6];   // (24, 32)
    const float* Wf  = (const float*)d_in[7];
    const float* bf  = (const float*)d_in[8];
    const float* fW1 = (const float*)d_in[9];
    const float* fb1 = (const float*)d_in[10];
    const float* fW2 = (const float*)d_in[11];
    const float* fb2 = (const float*)d_in[12];
    float* out = (float*)d_out;

    static bool attr_done = false;
    if (!attr_done) {
        cudaFuncSetAttribute(chain_kernel,
            cudaFuncAttributeMaxDynamicSharedMemorySize, SMEM_BYTES);
        attr_done = true;
    }

    // 24 layers (layer 0 computes h_init from x) + fused pool, one grid
    chain_kernel<<<NGRID, NTHR, SMEM_BYTES>>>(x, W0, b0, Wd, bd, W1, b1, Wf, bf);

    // FC head with PDL: weight staging overlaps the chain tail
    cudaLaunchAttribute pdl[1];
    pdl[0].id = cudaLaunchAttributeProgrammaticStreamSerialization;
    pdl[0].val.programmaticStreamSerializationAllowed = 1;
    cudaLaunchConfig_t cfgF = {};
    cfgF.gridDim  = dim3(B_);
    cfgF.blockDim = dim3(64);
    cfgF.dynamicSmemBytes = 0;
    cfgF.stream = 0;
    cfgF.attrs = pdl;
    cfgF.numAttrs = 1;
    cudaLaunchKernelEx(&cfgF, fc_kernel, fW1, fb1, fW2, fb2, out);
}